// round 4
// baseline (speedup 1.0000x reference)
#include <cuda_runtime.h>

#define TPB 128
#define SPT 4
// dynamic smem layout (bytes):
//   [0,1664)    sw1: 26*8 packed weight pairs (ull)
//   [1664,1728) sb1p: 8 packed bias pairs
//   [1728,1792) sw2: 16 floats
//   [1792,1796) sb2
//   [2048, 2048+4*12288) staging: per warp 3 tables * 4 samples * 32 rows * 32B
#define STAGE_BASE 2048
#define WARP_STAGE 12288
#define SMEM_TOTAL (STAGE_BASE + 4 * WARP_STAGE)   // 51200

typedef unsigned long long ull;

__device__ __forceinline__ ull pack2(float lo, float hi) {
    ull r;
    asm("mov.b64 %0, {%1, %2};" : "=l"(r) : "f"(lo), "f"(hi));
    return r;
}
__device__ __forceinline__ void unpack2(ull v, float& lo, float& hi) {
    asm("mov.b64 {%0, %1}, %2;" : "=f"(lo), "=f"(hi) : "l"(v));
}
__device__ __forceinline__ ull fma2(ull a, ull b, ull c) {
    ull d;
    asm("fma.rn.f32x2 %0, %1, %2, %3;" : "=l"(d) : "l"(a), "l"(b), "l"(c));
    return d;
}
__device__ __forceinline__ unsigned sw128(unsigned off) {
    return off ^ ((off >> 3) & 0x70u);   // XOR bits[4:7) with bits[7:10)
}

__global__ __launch_bounds__(TPB, 4) void dlrm_kernel(
    const int*    __restrict__ user_id,
    const int*    __restrict__ item_id,
    const int*    __restrict__ cat_id,
    const float2* __restrict__ dense,
    const float*  __restrict__ user_t,   // [NUM_USERS, 8]
    const float*  __restrict__ item_t,
    const float*  __restrict__ cat_t,
    const float*  __restrict__ w1,       // [26,16] row-major
    const float*  __restrict__ b1,
    const float*  __restrict__ w2,
    const float*  __restrict__ b2,
    float*        __restrict__ out,
    int batch)
{
    extern __shared__ __align__(128) char smem[];
    ull*   sw1  = (ull*)smem;
    ull*   sb1p = (ull*)(smem + 1664);
    float* sw2  = (float*)(smem + 1728);
    float* sb2p = (float*)(smem + 1792);

    {
        const ull* w1u = (const ull*)w1;
        for (int k = threadIdx.x; k < 26 * 8; k += TPB) sw1[k] = w1u[k];
        if (threadIdx.x < 8)  sb1p[threadIdx.x] = ((const ull*)b1)[threadIdx.x];
        if (threadIdx.x < 16) sw2[threadIdx.x]  = w2[threadIdx.x];
        if (threadIdx.x == 0) sb2p[0] = b2[0];
    }
    __syncthreads();

    const int lane = threadIdx.x & 31;
    const int warp = threadIdx.x >> 5;
    char* stage = smem + STAGE_BASE + warp * WARP_STAGE;

    const int s0 = blockIdx.x * (TPB * SPT) + threadIdx.x;
    if (s0 >= batch) return;  // never taken: batch divisible by TPB*SPT

    // ---- coalesced id/dense loads ----
    int ids[3][SPT];
    float2 dn[SPT];
    const int* __restrict__ idp[3] = { user_id, item_id, cat_id };
#pragma unroll
    for (int s = 0; s < SPT; s++) {
        int idx = s0 + s * TPB;
        ids[0][s] = idp[0][idx];
        ids[1][s] = idp[1][idx];
        ids[2][s] = idp[2][idx];
        dn[s] = dense[idx];
    }

    const float* __restrict__ tabs[3] = { user_t, item_t, cat_t };

    // ---- cooperative gather: lanes 2k,2k+1 fetch the two 16B halves of one
    // row -> each 128B line touched by exactly one instruction. Two sub-steps
    // cover owners 0..15 and 16..31 of each (table, sample) group. ----
    const int h    = lane & 1;    // which 16B half this lane fetches
    const int rsel = lane >> 1;   // row 0..15 within sub-step
#pragma unroll
    for (int T = 0; T < 3; T++) {
#pragma unroll
        for (int s = 0; s < SPT; s++) {
            int idA = __shfl_sync(0xFFFFFFFFu, ids[T][s], rsel);
            int idB = __shfl_sync(0xFFFFFFFFu, ids[T][s], 16 + rsel);
            float4 vA = *((const float4*)(tabs[T] + 8 * (long)idA) + h);
            float4 vB = *((const float4*)(tabs[T] + 8 * (long)idB) + h);
            unsigned offA = (unsigned)(((T * 4 + s) * 32 + rsel) * 32 + 16 * h);
            unsigned offB = (unsigned)(((T * 4 + s) * 32 + 16 + rsel) * 32 + 16 * h);
            *(float4*)(stage + sw128(offA)) = vA;
            *(float4*)(stage + sw128(offB)) = vB;
        }
    }
    __syncwarp();

    // Swizzled base of this lane's own staged rows, per (table, sample).
    // phys(i) = rbase ^ (4*(i&7)) is exact: row base has bits[0:5)=0 and the
    // swizzle key doesn't depend on i.
    unsigned rbase[3][SPT];
#pragma unroll
    for (int T = 0; T < 3; T++)
#pragma unroll
        for (int s = 0; s < SPT; s++) {
            unsigned off = (unsigned)(((T * 4 + s) * 32 + lane) * 32);
            rbase[T][s] = sw128(off);
        }

    // ---- layer 1: acc[s][jp] = (h[2jp], h[2jp+1]) in f32x2 lanes ----
    ull acc[SPT][8];
    {
        ull b[8];
#pragma unroll
        for (int j = 0; j < 8; j++) b[j] = sb1p[j];
#pragma unroll
        for (int s = 0; s < SPT; s++)
#pragma unroll
            for (int j = 0; j < 8; j++) acc[s][j] = b[j];
    }

#pragma unroll
    for (int i = 0; i < 26; i++) {
        const ulonglong2* wrow = (const ulonglong2*)&sw1[i * 8];
        ulonglong2 w01 = wrow[0];
        ulonglong2 w23 = wrow[1];
        ulonglong2 w45 = wrow[2];
        ulonglong2 w67 = wrow[3];
#pragma unroll
        for (int s = 0; s < SPT; s++) {
            float f;
            if (i < 24) {
                const int T = i >> 3;
                f = *(const float*)(stage + (rbase[T][s] ^ (unsigned)(4 * (i & 7))));
            } else {
                f = (i == 24) ? dn[s].x : dn[s].y;
            }
            ull p = pack2(f, f);
            acc[s][0] = fma2(p, w01.x, acc[s][0]);
            acc[s][1] = fma2(p, w01.y, acc[s][1]);
            acc[s][2] = fma2(p, w23.x, acc[s][2]);
            acc[s][3] = fma2(p, w23.y, acc[s][3]);
            acc[s][4] = fma2(p, w45.x, acc[s][4]);
            acc[s][5] = fma2(p, w45.y, acc[s][5]);
            acc[s][6] = fma2(p, w67.x, acc[s][6]);
            acc[s][7] = fma2(p, w67.y, acc[s][7]);
        }
    }

    // ---- relu + layer 2 + sigmoid ----
    float sb2v = sb2p[0];
#pragma unroll
    for (int s = 0; s < SPT; s++) {
        float l = sb2v;
#pragma unroll
        for (int j = 0; j < 8; j++) {
            float h0, h1;
            unpack2(acc[s][j], h0, h1);
            l = fmaf(fmaxf(h0, 0.0f), sw2[2 * j],     l);
            l = fmaf(fmaxf(h1, 0.0f), sw2[2 * j + 1], l);
        }
        float e = __expf(-l);
        out[s0 + s * TPB] = __fdividef(1.0f, 1.0f + e);
    }
}

extern "C" void kernel_launch(void* const* d_in, const int* in_sizes, int n_in,
                              void* d_out, int out_size) {
    const int*    user_id = (const int*)d_in[0];
    const int*    item_id = (const int*)d_in[1];
    const int*    cat_id  = (const int*)d_in[2];
    const float2* dense   = (const float2*)d_in[3];
    const float*  user_t  = (const float*)d_in[4];
    const float*  item_t  = (const float*)d_in[5];
    const float*  cat_t   = (const float*)d_in[6];
    const float*  w1      = (const float*)d_in[7];
    const float*  b1      = (const float*)d_in[8];
    const float*  w2      = (const float*)d_in[9];
    const float*  b2      = (const float*)d_in[10];
    float*        out     = (float*)d_out;

    static int attr_done = 0;
    // idempotent, deterministic: safe to call every launch
    cudaFuncSetAttribute(dlrm_kernel, cudaFuncAttributeMaxDynamicSharedMemorySize,
                         SMEM_TOTAL);
    (void)attr_done;

    const int batch = in_sizes[0];
    const int per_block = TPB * SPT;
    const int blocks = (batch + per_block - 1) / per_block;

    dlrm_kernel<<<blocks, TPB, SMEM_TOTAL>>>(user_id, item_id, cat_id, dense,
                                             user_t, item_t, cat_t,
                                             w1, b1, w2, b2, out, batch);
}

// round 5
// speedup vs baseline: 1.8496x; 1.8496x over previous
#include <cuda_runtime.h>

#define TPB 128
#define SPT 4

typedef unsigned long long ull;

__constant__ ull   cw1[26 * 8];   // (w1[i][2j], w1[i][2j+1]) packed pairs
__constant__ ull   cb1p[8];       // (b1[2j], b1[2j+1])
__constant__ float cw2[16];
__constant__ float cb2[1];

__device__ __forceinline__ ull pack2(float lo, float hi) {
    ull r;
    asm("mov.b64 %0, {%1, %2};" : "=l"(r) : "f"(lo), "f"(hi));
    return r;
}
__device__ __forceinline__ void unpack2(ull v, float& lo, float& hi) {
    asm("mov.b64 {%0, %1}, %2;" : "=f"(lo), "=f"(hi) : "l"(v));
}
__device__ __forceinline__ ull fma2(ull a, ull b, ull c) {
    ull d;
    asm("fma.rn.f32x2 %0, %1, %2, %3;" : "=l"(d) : "l"(a), "l"(b), "l"(c));
    return d;
}
__device__ __forceinline__ float getc(float4 v, int k) {
    return (k == 0) ? v.x : (k == 1) ? v.y : (k == 2) ? v.z : v.w;
}

__global__ __launch_bounds__(TPB, 2) void dlrm_kernel(
    const int*    __restrict__ user_id,
    const int*    __restrict__ item_id,
    const int*    __restrict__ cat_id,
    const float2* __restrict__ dense,
    const float4* __restrict__ user_t,   // [NUM_USERS, 8] as [., 2] float4
    const float4* __restrict__ item_t,
    const float4* __restrict__ cat_t,
    float*        __restrict__ out,
    int batch)
{
    const int lane = threadIdx.x & 31;
    const int h    = lane & 1;           // which 16B half this lane fetches
    const bool odd = (h != 0);

    const int s0 = blockIdx.x * (TPB * SPT) + threadIdx.x;
    if (s0 >= batch) return;  // never taken: batch % (TPB*SPT) == 0

    // ---- coalesced id/dense loads ----
    int ids[3][SPT];
    float2 dn[SPT];
#pragma unroll
    for (int s = 0; s < SPT; s++) {
        int idx = s0 + s * TPB;
        ids[0][s] = user_id[idx];
        ids[1][s] = item_id[idx];
        ids[2][s] = cat_id[idx];
        dn[s]     = dense[idx];
    }

    // ---- cooperative pairwise gather, ALL 24 loads issued up front (MLP=24).
    // Lanes 2k and 2k+1 each fetch one 16B half of BOTH rows of the pair:
    // every 128B line is touched by exactly one instruction (2 lanes coalesce).
    float4 rA[12], rB[12];   // rA: even lane's row halves, rB: odd lane's row
#pragma unroll
    for (int g = 0; g < 12; g++) {
        const int T = g >> 2, s = g & 3;
        const float4* tab = (T == 0) ? user_t : (T == 1) ? item_t : cat_t;
        int idE = __shfl_sync(0xFFFFFFFFu, ids[T][s], lane & ~1);
        int idO = __shfl_sync(0xFFFFFFFFu, ids[T][s], lane | 1);
        rA[g] = tab[2 * (long)idE + h];
        rB[g] = tab[2 * (long)idO + h];
    }

    // ---- layer 1 accumulators: acc[s][jp] = (h[2jp], h[2jp+1]) ----
    ull acc[SPT][8];
#pragma unroll
    for (int j = 0; j < 8; j++) {
        ull b = cb1p[j];
#pragma unroll
        for (int s = 0; s < SPT; s++) acc[s][j] = b;
    }

#pragma unroll
    for (int T = 0; T < 3; T++) {
        // exchange halves within lane pairs: after this, lo[s]=f[8T..8T+3],
        // hi[s]=f[8T+4..8T+7] of this lane's own sample s
        float4 lo[SPT], hi[SPT];
#pragma unroll
        for (int s = 0; s < SPT; s++) {
            const int g = T * 4 + s;
            float4 send = odd ? rA[g] : rB[g];
            float4 own  = odd ? rB[g] : rA[g];
            float4 recv;
            recv.x = __shfl_xor_sync(0xFFFFFFFFu, send.x, 1);
            recv.y = __shfl_xor_sync(0xFFFFFFFFu, send.y, 1);
            recv.z = __shfl_xor_sync(0xFFFFFFFFu, send.z, 1);
            recv.w = __shfl_xor_sync(0xFFFFFFFFu, send.w, 1);
            lo[s] = odd ? recv : own;
            hi[s] = odd ? own  : recv;
        }
        // FMA block: weights from __constant__ (uniform -> LDCU, off the L1 path)
#pragma unroll
        for (int ii = 0; ii < 8; ii++) {
            const int i = T * 8 + ii;
            ull w0 = cw1[i * 8 + 0], w1v = cw1[i * 8 + 1];
            ull w2v = cw1[i * 8 + 2], w3 = cw1[i * 8 + 3];
            ull w4 = cw1[i * 8 + 4], w5 = cw1[i * 8 + 5];
            ull w6 = cw1[i * 8 + 6], w7 = cw1[i * 8 + 7];
#pragma unroll
            for (int s = 0; s < SPT; s++) {
                float fv = (ii < 4) ? getc(lo[s], ii) : getc(hi[s], ii - 4);
                ull p = pack2(fv, fv);
                acc[s][0] = fma2(p, w0,  acc[s][0]);
                acc[s][1] = fma2(p, w1v, acc[s][1]);
                acc[s][2] = fma2(p, w2v, acc[s][2]);
                acc[s][3] = fma2(p, w3,  acc[s][3]);
                acc[s][4] = fma2(p, w4,  acc[s][4]);
                acc[s][5] = fma2(p, w5,  acc[s][5]);
                acc[s][6] = fma2(p, w6,  acc[s][6]);
                acc[s][7] = fma2(p, w7,  acc[s][7]);
            }
        }
    }

    // ---- dense features i = 24, 25 ----
#pragma unroll
    for (int ii = 0; ii < 2; ii++) {
        const int i = 24 + ii;
        ull w0 = cw1[i * 8 + 0], w1v = cw1[i * 8 + 1];
        ull w2v = cw1[i * 8 + 2], w3 = cw1[i * 8 + 3];
        ull w4 = cw1[i * 8 + 4], w5 = cw1[i * 8 + 5];
        ull w6 = cw1[i * 8 + 6], w7 = cw1[i * 8 + 7];
#pragma unroll
        for (int s = 0; s < SPT; s++) {
            float fv = (ii == 0) ? dn[s].x : dn[s].y;
            ull p = pack2(fv, fv);
            acc[s][0] = fma2(p, w0,  acc[s][0]);
            acc[s][1] = fma2(p, w1v, acc[s][1]);
            acc[s][2] = fma2(p, w2v, acc[s][2]);
            acc[s][3] = fma2(p, w3,  acc[s][3]);
            acc[s][4] = fma2(p, w4,  acc[s][4]);
            acc[s][5] = fma2(p, w5,  acc[s][5]);
            acc[s][6] = fma2(p, w6,  acc[s][6]);
            acc[s][7] = fma2(p, w7,  acc[s][7]);
        }
    }

    // ---- relu + layer 2 + sigmoid ----
    const float sb2v = cb2[0];
#pragma unroll
    for (int s = 0; s < SPT; s++) {
        float l = sb2v;
#pragma unroll
        for (int j = 0; j < 8; j++) {
            float h0, h1;
            unpack2(acc[s][j], h0, h1);
            l = fmaf(fmaxf(h0, 0.0f), cw2[2 * j],     l);
            l = fmaf(fmaxf(h1, 0.0f), cw2[2 * j + 1], l);
        }
        float e = __expf(-l);
        out[s0 + s * TPB] = __fdividef(1.0f, 1.0f + e);
    }
}

extern "C" void kernel_launch(void* const* d_in, const int* in_sizes, int n_in,
                              void* d_out, int out_size) {
    const int*    user_id = (const int*)d_in[0];
    const int*    item_id = (const int*)d_in[1];
    const int*    cat_id  = (const int*)d_in[2];
    const float2* dense   = (const float2*)d_in[3];
    const float4* user_t  = (const float4*)d_in[4];
    const float4* item_t  = (const float4*)d_in[5];
    const float4* cat_t   = (const float4*)d_in[6];
    const float*  w1      = (const float*)d_in[7];
    const float*  b1      = (const float*)d_in[8];
    const float*  w2      = (const float*)d_in[9];
    const float*  b2      = (const float*)d_in[10];
    float*        out     = (float*)d_out;

    // D2D memcpys into __constant__ symbols: graph-capturable memcpy nodes,
    // no allocation, deterministic (re-run on every replay).
    cudaMemcpyToSymbolAsync(cw1,  w1, 26 * 16 * sizeof(float), 0,
                            cudaMemcpyDeviceToDevice, 0);
    cudaMemcpyToSymbolAsync(cb1p, b1, 16 * sizeof(float), 0,
                            cudaMemcpyDeviceToDevice, 0);
    cudaMemcpyToSymbolAsync(cw2,  w2, 16 * sizeof(float), 0,
                            cudaMemcpyDeviceToDevice, 0);
    cudaMemcpyToSymbolAsync(cb2,  b2, 1 * sizeof(float), 0,
                            cudaMemcpyDeviceToDevice, 0);

    const int batch = in_sizes[0];
    const int per_block = TPB * SPT;
    const int blocks = (batch + per_block - 1) / per_block;

    dlrm_kernel<<<blocks, TPB>>>(user_id, item_id, cat_id, dense,
                                 user_t, item_t, cat_t, out, batch);
}